// round 15
// baseline (speedup 1.0000x reference)
#include <cuda_runtime.h>
#include <cuda_bf16.h>

// LSTMPolicy via mma.sync m16n8k16 bf16 3-pass hi/lo split.
// R14: 512 threads/CTA (16 warps = 8 M-pos x 2 N-groups, M=16 rows/warp) for
// 4 warps/SMSP latency hiding. Same 512 CTAs, same weight images/staging.
// Zero init state => Whh* dead, f-gate dead (c = sigm(i)*tanh(g)).

#define BATCH   65536
#define NACT    16
#define TPB     512
#define NBLK    512

#define L0_CHUNK 13824            // 48 rows x 144 x 2
#define L1_CHUNK 26112            // 48 rows x 272 x 2
#define HD_CHUNK 13056            // 24 rows x 272 x 2
#define OFF_L1   110592
#define OFF_HD   319488
#define WIMG_BYTES 332544

__device__ __align__(16) unsigned char g_wimg[WIMG_BYTES];
__device__ float g_bc0[384];
__device__ float g_bc1[384];
__device__ float g_bch[32];

#define H0HI 3200
#define H0LO 38016
#define H1HI 72832
#define H1LO 107648
#define SWB  142464
#define SMEM_TOTAL 220800

static __device__ __forceinline__ unsigned smem_u32(const void* p) {
    unsigned a;
    asm("{ .reg .u64 t; cvta.to.shared.u64 t, %1; cvt.u32.u64 %0, t; }" : "=r"(a) : "l"(p));
    return a;
}
static __device__ __forceinline__ float tanh_ap(float x) {
    float y; asm("tanh.approx.f32 %0, %1;" : "=f"(y) : "f"(x)); return y;
}
static __device__ __forceinline__ float sigm(float x) {
    return fmaf(0.5f, tanh_ap(0.5f * x), 0.5f);
}
static __device__ __forceinline__ unsigned pack_bf16(float a, float b) {
    return (unsigned)__bfloat16_as_ushort(__float2bfloat16_rn(a)) |
           ((unsigned)__bfloat16_as_ushort(__float2bfloat16_rn(b)) << 16);
}
static __device__ __forceinline__ float bflo(float a) {
    return a - __bfloat162float(__float2bfloat16_rn(a));
}

#define LDSM4(r, ad) asm volatile( \
    "ldmatrix.sync.aligned.m8n8.x4.shared.b16 {%0,%1,%2,%3}, [%4];" \
    : "=r"((r)[0]),"=r"((r)[1]),"=r"((r)[2]),"=r"((r)[3]) : "r"(ad))
#define LDSM2(r0, r1, ad) asm volatile( \
    "ldmatrix.sync.aligned.m8n8.x2.shared.b16 {%0,%1}, [%2];" \
    : "=r"(r0), "=r"(r1) : "r"(ad))
#define MMA(c, a, b0, b1) asm volatile( \
    "mma.sync.aligned.m16n8k16.row.col.f32.bf16.bf16.f32 " \
    "{%0,%1,%2,%3}, {%4,%5,%6,%7}, {%8,%9}, {%0,%1,%2,%3};" \
    : "+f"((c)[0]),"+f"((c)[1]),"+f"((c)[2]),"+f"((c)[3]) \
    : "r"((a)[0]),"r"((a)[1]),"r"((a)[2]),"r"((a)[3]), "r"(b0),"r"(b1))
#define STS32(ad, v) asm volatile("st.shared.b32 [%0], %1;" :: "r"(ad), "r"(v) : "memory")

static __device__ __forceinline__ void stage(unsigned sdst, const unsigned char* gsrc,
                                             int granules, int tid) {
    for (int i = tid; i < granules; i += TPB)
        asm volatile("cp.async.cg.shared.global [%0], [%1], 16;"
                     :: "r"(sdst + i * 16), "l"(gsrc + (size_t)i * 16));
    asm volatile("cp.async.commit_group;" ::: "memory");
}

// ======================= weight-prep kernel =======================
__global__ void prep_weights(const float* __restrict__ W0, const float* __restrict__ W1,
                             const float* __restrict__ Wp, const float* __restrict__ Wv,
                             const float* __restrict__ bih0, const float* __restrict__ bhh0,
                             const float* __restrict__ bih1, const float* __restrict__ bhh1,
                             const float* __restrict__ bp,  const float* __restrict__ bv) {
    int id = blockIdx.x * 256 + threadIdx.x;
    if (id < 20784) {
        float w[8];
        #pragma unroll
        for (int j = 0; j < 8; j++) w[j] = 0.0f;
        int half; unsigned addr;
        if (id < 6912) {                                  // L0: 8 chunks, rows 144B
            int c = id / 864, q = id % 864;
            half = q / 432; q %= 432;
            int r = q / 9, gi = q % 9;
            addr = c * L0_CHUNK + half * 6912 + r * 144 + gi * 16;
            if (gi < 8) {
                int gate = r / 16, j = r % 16;
                int sr = (gate == 0) ? 16*c + j : (gate == 1) ? 256 + 16*c + j : 384 + 16*c + j;
                #pragma unroll
                for (int t = 0; t < 8; t++) w[t] = W0[sr * 64 + gi * 8 + t];
            }
        } else if (id < 19968) {                          // L1: 8 chunks, rows 272B
            int i = id - 6912;
            int c = i / 1632, q = i % 1632;
            half = q / 816; q %= 816;
            int r = q / 17, gi = q % 17;
            addr = OFF_L1 + c * L1_CHUNK + half * 13056 + r * 272 + gi * 16;
            if (gi < 16) {
                int gate = r / 16, j = r % 16;
                int sr = (gate == 0) ? 16*c + j : (gate == 1) ? 256 + 16*c + j : 384 + 16*c + j;
                #pragma unroll
                for (int t = 0; t < 8; t++) w[t] = W1[sr * 128 + gi * 8 + t];
            }
        } else {                                          // heads: 24 rows [Wp16, Wv, 0x7]
            int i = id - 19968;
            half = i / 408;
            int q = i % 408, r = q / 17, gi = q % 17;
            addr = OFF_HD + half * 6528 + r * 272 + gi * 16;
            if (gi < 16 && r <= 16) {
                #pragma unroll
                for (int t = 0; t < 8; t++)
                    w[t] = (r < 16) ? Wp[r * 128 + gi * 8 + t] : Wv[gi * 8 + t];
            }
        }
        unsigned v[4];
        #pragma unroll
        for (int j = 0; j < 4; j++) {
            float a = w[2*j], b = w[2*j+1];
            if (half) { a = bflo(a); b = bflo(b); }
            v[j] = pack_bf16(a, b);
        }
        *reinterpret_cast<uint4*>(g_wimg + addr) = make_uint4(v[0], v[1], v[2], v[3]);
    } else if (id < 21584) {
        int i = id - 20784;
        if (i < 384) {
            int gate = i / 128, k = i % 128;
            int sr = (gate == 0) ? k : (gate == 1) ? 256 + k : 384 + k;
            g_bc0[i] = bih0[sr] + bhh0[sr];
        } else if (i < 768) {
            int j = i - 384, gate = j / 128, k = j % 128;
            int sr = (gate == 0) ? k : (gate == 1) ? 256 + k : 384 + k;
            g_bc1[j] = bih1[sr] + bhh1[sr];
        } else {
            int n = i - 768;
            g_bch[n] = (n < NACT) ? bp[n] : (n == NACT) ? bv[0] : 0.0f;
        }
    }
}

// ======================= main fused kernel =======================
__global__ __launch_bounds__(TPB, 1)
void lstm_mma(const float* __restrict__ x, float* __restrict__ out) {
    extern __shared__ __align__(16) char sm[];
    const unsigned sb = smem_u32(sm);
    const int tid  = threadIdx.x;
    const int warp = tid >> 5, lane = tid & 31;
    const int wm = warp & 7, wg = warp >> 3;          // 8 M-positions x 2 N-groups
    const int mrow = lane & 7, msel = lane >> 3;
    const int t4 = lane >> 2, kp = (lane & 3) * 2;
    float* bias_sm = reinterpret_cast<float*>(sm);

    for (int i = tid; i < 800; i += TPB)
        bias_sm[i] = (i < 384) ? g_bc0[i] : (i < 768) ? g_bc1[i - 384] : g_bch[i - 768];

    stage(sb + SWB, g_wimg, L0_CHUNK / 16, tid);

    // ---- x fragments: gmem -> registers (hi/lo), M=16 rows/warp, K=64 ----
    unsigned AH[4][4], AL[4][4];
    {
        const float* xb = x + ((size_t)blockIdx.x * 128 + 16 * wm + t4) * 64;
        #pragma unroll
        for (int rr = 0; rr < 2; rr++) {                  // rows t4 + 8*rr
            const float* xr = xb + rr * 8 * 64;
            #pragma unroll
            for (int kk = 0; kk < 4; kk++) {
                float2 u = __ldg(reinterpret_cast<const float2*>(xr + 16*kk + kp));
                float2 v = __ldg(reinterpret_cast<const float2*>(xr + 16*kk + kp + 8));
                AH[kk][rr]     = pack_bf16(u.x, u.y);
                AH[kk][2 + rr] = pack_bf16(v.x, v.y);
                AL[kk][rr]     = pack_bf16(bflo(u.x), bflo(u.y));
                AL[kk][2 + rr] = pack_bf16(bflo(v.x), bflo(v.y));
            }
        }
    }

    const unsigned aoff = (unsigned)(16*wm + ((msel & 1) << 3) + mrow) * 272 + ((msel >> 1) << 4);
    const unsigned bsel = (unsigned)((msel & 1) << 4);

    for (int ci = 0; ci < 17; ci++) {
        if (ci < 16) {
            int nx = ci + 1;
            unsigned dst = sb + SWB + (unsigned)(nx % 3) * 26112;
            const unsigned char* src; int gran;
            if (nx < 8)       { src = g_wimg + nx * L0_CHUNK;             gran = L0_CHUNK / 16; }
            else if (nx < 16) { src = g_wimg + OFF_L1 + (nx-8)*L1_CHUNK;  gran = L1_CHUNK / 16; }
            else              { src = g_wimg + OFF_HD;                    gran = HD_CHUNK / 16; }
            stage(dst, src, gran, tid);
            asm volatile("cp.async.wait_group 1;" ::: "memory");
        } else {
            asm volatile("cp.async.wait_group 0;" ::: "memory");
        }
        __syncthreads();

        const unsigned swb = sb + SWB + (unsigned)(ci % 3) * 26112;

        if (ci < 16) {
            const bool l0 = ci < 8;
            const int  c  = l0 ? ci : ci - 8;
            const int  col0 = 16 * c + 8 * wg + kp;
            const float* bs = bias_sm + (l0 ? 0 : 384);
            const unsigned dsth = sb + (l0 ? H0HI : H1HI);
            const unsigned dstl = sb + (l0 ? H0LO : H1LO);

            float acc[3][4];
            #pragma unroll
            for (int g = 0; g < 3; g++) {
                float b0 = bs[g * 128 + col0], b1 = bs[g * 128 + col0 + 1];
                acc[g][0] = b0; acc[g][1] = b1; acc[g][2] = b0; acc[g][3] = b1;
            }

            if (l0) {
                // A in registers, K=64, weights rows 144B
                unsigned bh[3][2], bl[3][2];
                #pragma unroll
                for (int kk = 0; kk < 4; kk++) {
                    #pragma unroll
                    for (int g = 0; g < 3; g++) {
                        unsigned ba = swb + (unsigned)(g*16 + 8*wg + mrow) * 144 + bsel + kk * 32;
                        LDSM2(bh[g][0], bh[g][1], ba);
                        LDSM2(bl[g][0], bl[g][1], ba + 6912);
                    }
                    #pragma unroll
                    for (int g = 0; g < 3; g++) MMA(acc[g], AH[kk], bh[g][0], bh[g][1]);
                    #pragma unroll
                    for (int g = 0; g < 3; g++) MMA(acc[g], AH[kk], bl[g][0], bl[g][1]);
                    #pragma unroll
                    for (int g = 0; g < 3; g++) MMA(acc[g], AL[kk], bh[g][0], bh[g][1]);
                }
            } else {
                // A = h0 via ldmatrix, K=128, rows 272B
                #pragma unroll
                for (int kk = 0; kk < 8; kk++) {
                    unsigned ah[4], al[4], bh[3][2], bl[3][2];
                    const unsigned ko = (unsigned)kk * 32;
                    LDSM4(ah, sb + H0HI + aoff + ko);
                    LDSM4(al, sb + H0LO + aoff + ko);
                    #pragma unroll
                    for (int g = 0; g < 3; g++) {
                        unsigned ba = swb + (unsigned)(g*16 + 8*wg + mrow) * 272 + bsel + ko;
                        LDSM2(bh[g][0], bh[g][1], ba);
                        LDSM2(bl[g][0], bl[g][1], ba + 13056);
                    }
                    #pragma unroll
                    for (int g = 0; g < 3; g++) MMA(acc[g], ah, bh[g][0], bh[g][1]);
                    #pragma unroll
                    for (int g = 0; g < 3; g++) MMA(acc[g], ah, bl[g][0], bl[g][1]);
                    #pragma unroll
                    for (int g = 0; g < 3; g++) MMA(acc[g], al, bh[g][0], bh[g][1]);
                }
            }

            // epilogue: activations -> h hi/lo into dst buffers
            #pragma unroll
            for (int e = 0; e < 2; e++) {
                float i0 = acc[0][2*e], i1 = acc[0][2*e + 1];
                float g0 = acc[1][2*e], g1 = acc[1][2*e + 1];
                float o0 = acc[2][2*e], o1 = acc[2][2*e + 1];
                float c0 = sigm(i0) * tanh_ap(g0), c1 = sigm(i1) * tanh_ap(g1);
                float h0 = sigm(o0) * tanh_ap(c0), h1 = sigm(o1) * tanh_ap(c1);
                int row = 16*wm + t4 + 8*e;
                unsigned off = (unsigned)row * 272 + (unsigned)col0 * 2;
                STS32(dsth + off, pack_bf16(h0, h1));
                STS32(dstl + off, pack_bf16(bflo(h0), bflo(h1)));
            }
        } else {
            // heads: A = h1. wg0 -> policy cols 0-7 + value; wg1 -> policy cols 8-15.
            float acc[2][4];
            {
                float p0 = bias_sm[768 + 8*wg + kp], p1 = bias_sm[768 + 8*wg + kp + 1];
                float v0 = bias_sm[768 + 16 + kp],   v1 = bias_sm[768 + 16 + kp + 1];
                acc[0][0] = p0; acc[0][1] = p1; acc[0][2] = p0; acc[0][3] = p1;
                acc[1][0] = v0; acc[1][1] = v1; acc[1][2] = v0; acc[1][3] = v1;
            }
            #pragma unroll
            for (int kk = 0; kk < 8; kk++) {
                unsigned ah[4], al[4];
                const unsigned ko = (unsigned)kk * 32;
                LDSM4(ah, sb + H1HI + aoff + ko);
                LDSM4(al, sb + H1LO + aoff + ko);

                unsigned bh0, bh1, bl0, bl1, ch0, ch1, cl0, cl1;
                unsigned ba = swb + (unsigned)(8*wg + mrow) * 272 + bsel + ko;
                LDSM2(bh0, bh1, ba);
                LDSM2(bl0, bl1, ba + 6528);
                if (wg == 0) {
                    unsigned ba2 = swb + (unsigned)(16 + mrow) * 272 + bsel + ko;
                    LDSM2(ch0, ch1, ba2);
                    LDSM2(cl0, cl1, ba2 + 6528);
                }
                MMA(acc[0], ah, bh0, bh1);
                if (wg == 0) MMA(acc[1], ah, ch0, ch1);
                MMA(acc[0], ah, bl0, bl1);
                if (wg == 0) MMA(acc[1], ah, cl0, cl1);
                MMA(acc[0], al, bh0, bh1);
                if (wg == 0) MMA(acc[1], al, ch0, ch1);
            }
            #pragma unroll
            for (int e = 0; e < 2; e++) {
                size_t r = (size_t)blockIdx.x * 128 + 16*wm + t4 + 8*e;
                float2 pv = make_float2(acc[0][2*e], acc[0][2*e + 1]);
                *reinterpret_cast<float2*>(out + r * NACT + 8*wg + kp) = pv;
                if (wg == 0 && (lane & 3) == 0)
                    out[(size_t)BATCH * NACT + r] = acc[1][2*e];
            }
        }
    }
}

extern "C" void kernel_launch(void* const* d_in, const int* in_sizes, int n_in,
                              void* d_out, int out_size) {
    const float* x    = (const float*)d_in[0];
    const float* Wih0 = (const float*)d_in[1];
    const float* bih0 = (const float*)d_in[3];
    const float* bhh0 = (const float*)d_in[4];
    const float* Wih1 = (const float*)d_in[5];
    const float* bih1 = (const float*)d_in[7];
    const float* bhh1 = (const float*)d_in[8];
    const float* Wp   = (const float*)d_in[9];
    const float* bp   = (const float*)d_in[10];
    const float* Wv   = (const float*)d_in[11];
    const float* bv   = (const float*)d_in[12];
    float* out = (float*)d_out;

    prep_weights<<<85, 256>>>(Wih0, Wih1, Wp, Wv, bih0, bhh0, bih1, bhh1, bp, bv);

    cudaFuncSetAttribute(lstm_mma, cudaFuncAttributeMaxDynamicSharedMemorySize, SMEM_TOTAL);
    lstm_mma<<<NBLK, TPB, SMEM_TOTAL>>>(x, out);
}